// round 2
// baseline (speedup 1.0000x reference)
#include <cuda_runtime.h>

// GRU_83906481094863 — fused persistent GRU recurrence on sm_100a.
// B=512, T=1024, D=46, H=128, gates=3H=384 (torch order r,z,n).
// 128 CTAs (one wave), 4 batch elements per CTA, 512 threads:
//   threads [0,384): gate threads — one (gate-row j) x 4 batches; W_hh dot via
//                    shared (k-major, LDS.128 conflict-free), W_ih row held in
//                    registers as packed f32x2; all MACs via fma.rn.f32x2.
//   threads [384,512): aux — prefetch x(t+1) from global, apply gate
//                    nonlinearities + h update.
// Double-buffered h and x in shared; two __syncthreads per step.

#define BB 512
#define TT 1024
#define DD 46
#define DP 48        // D padded to multiple of 4 (pads are zero)
#define HH 128
#define GG 384       // 3*H
#define NB 4         // batches per CTA
#define NCTA (BB/NB) // 128
#define NTHR 512

// Shared layout (floats):
//  sW  [49152)           W_hh staged k-chunk-major: float4 index (kc*GG + j)
//  sH  [1024)            h double buffer [2][NB][HH]
//  sX  [384)             x double buffer [2][NB][DP]
//  sRZ [1024)            r/z preactivations [NB][2*HH]
//  sXN [512)             x_n part [NB][HH]
//  sGN [512)             g_n part [NB][HH]
#define SMEM_FLOATS (49152 + 1024 + 384 + 1024 + 512 + 512)
#define SMEM_BYTES  (SMEM_FLOATS * 4)

__device__ __forceinline__ void fma2(unsigned long long &d,
                                     unsigned long long a,
                                     unsigned long long b) {
    // packed fp32x2 FMA (Blackwell sm_100+): d = a*b + d elementwise
    asm("fma.rn.f32x2 %0, %1, %2, %0;" : "+l"(d) : "l"(a), "l"(b));
}

__device__ __forceinline__ float sum2(unsigned long long v) {
    float lo, hi;
    asm("mov.b64 {%0, %1}, %2;" : "=f"(lo), "=f"(hi) : "l"(v));
    return lo + hi;
}

__device__ __forceinline__ unsigned long long pack2(float lo, float hi) {
    unsigned long long v;
    asm("mov.b64 %0, {%1, %2};" : "=l"(v) : "f"(lo), "f"(hi));
    return v;
}

__device__ __forceinline__ float sigf(float x) {
    // accurate sigmoid via tanhf (fp32)
    return 0.5f + 0.5f * tanhf(0.5f * x);
}

__global__ void __launch_bounds__(NTHR, 1) gru_fused_kernel(
    const float* __restrict__ history,  // [B][T][D]
    const float* __restrict__ W_ih,     // [3H][D]
    const float* __restrict__ W_hh,     // [3H][H]
    const float* __restrict__ b_ih,     // [3H]
    const float* __restrict__ b_hh,     // [3H]
    const float* __restrict__ h0,       // [H] (broadcast over batch)
    float* __restrict__ out)            // [B][H]
{
    extern __shared__ float smem[];
    float* sW  = smem;
    float* sH  = smem + 49152;
    float* sX  = sH + 1024;
    float* sRZ = sX + 384;
    float* sXN = sRZ + 1024;
    float* sGN = sXN + 512;

    const int tid = threadIdx.x;
    const int b0  = blockIdx.x * NB;

    // ---- stage W_hh k-chunk-major into shared ----
    // sW as float4[kc][GG]: component (k&3) of float4 (k>>2)*GG + j
    for (int idx = tid; idx < GG * HH; idx += NTHR) {
        int j = idx >> 7;       // row (gate)
        int k = idx & 127;      // k within H
        sW[((k >> 2) * GG + j) * 4 + (k & 3)] = W_hh[idx];
    }

    // ---- init h buffer 0: h0 broadcast over the 4 batches ----
    // NB*HH == 512 == NTHR
    sH[tid] = h0[tid & 127];

    // ---- zero the x padding slots (both buffers), race-free ----
    if (tid < 16) {
        int buf = tid >> 3, nb = (tid >> 1) & 3, d = DD + (tid & 1);
        sX[buf * (NB * DP) + nb * DP + d] = 0.f;
    }

    // ---- load x(t=0) into buffer 0 ----
    for (int idx = tid; idx < NB * DD; idx += NTHR) {
        int nb = idx / DD, d = idx - nb * DD;
        sX[nb * DP + d] = history[(size_t)(b0 + nb) * (TT * DD) + d];
    }

    // ---- gate-thread private state: W_ih row packed as f32x2, biases ----
    unsigned long long wih[24];
    float bihv = 0.f, bhhv = 0.f;
    const int j = tid;
    if (tid < GG) {
        bihv = b_ih[j];
        bhhv = b_hh[j];
        #pragma unroll
        for (int p = 0; p < 23; p++)
            wih[p] = pack2(W_ih[j * DD + 2 * p], W_ih[j * DD + 2 * p + 1]);
        wih[23] = 0ull;  // pads k=46,47
    }

    // per-thread W-row base pointer for the kc loop (hoist index math)
    const ulonglong2* wrow = (const ulonglong2*)sW + j;

    __syncthreads();

    for (int t = 0; t < TT; t++) {
        const int cur = t & 1, nxt = cur ^ 1;

        if (tid < GG) {
            // ---------- gate phase: dots for 4 batches ----------
            const float* hb = sH + cur * (NB * HH);
            const float* xb = sX + cur * (NB * DP);
            unsigned long long ah0 = 0, ah1 = 0, ah2 = 0, ah3 = 0; // hh dots
            unsigned long long ai0 = 0, ai1 = 0, ai2 = 0, ai3 = 0; // ih dots

            #pragma unroll 8
            for (int kc = 0; kc < 32; kc++) {
                ulonglong2 w = wrow[kc * GG];              // W row chunk (coalesced)
                ulonglong2 hA = *(const ulonglong2*)(hb + 0 * HH + kc * 4);
                ulonglong2 hB = *(const ulonglong2*)(hb + 1 * HH + kc * 4);
                ulonglong2 hC = *(const ulonglong2*)(hb + 2 * HH + kc * 4);
                ulonglong2 hD = *(const ulonglong2*)(hb + 3 * HH + kc * 4);
                fma2(ah0, w.x, hA.x); fma2(ah1, w.x, hB.x);
                fma2(ah2, w.x, hC.x); fma2(ah3, w.x, hD.x);
                fma2(ah0, w.y, hA.y); fma2(ah1, w.y, hB.y);
                fma2(ah2, w.y, hC.y); fma2(ah3, w.y, hD.y);
            }
            #pragma unroll
            for (int q = 0; q < 12; q++) {
                ulonglong2 xA = *(const ulonglong2*)(xb + 0 * DP + 4 * q);
                ulonglong2 xB = *(const ulonglong2*)(xb + 1 * DP + 4 * q);
                ulonglong2 xC = *(const ulonglong2*)(xb + 2 * DP + 4 * q);
                ulonglong2 xD = *(const ulonglong2*)(xb + 3 * DP + 4 * q);
                fma2(ai0, wih[2*q],   xA.x); fma2(ai1, wih[2*q],   xB.x);
                fma2(ai2, wih[2*q],   xC.x); fma2(ai3, wih[2*q],   xD.x);
                fma2(ai0, wih[2*q+1], xA.y); fma2(ai1, wih[2*q+1], xB.y);
                fma2(ai2, wih[2*q+1], xC.y); fma2(ai3, wih[2*q+1], xD.y);
            }

            float sh[NB] = { sum2(ah0), sum2(ah1), sum2(ah2), sum2(ah3) };
            float si[NB] = { sum2(ai0), sum2(ai1), sum2(ai2), sum2(ai3) };

            if (j < 2 * HH) {
                // r / z rows: combined preactivation, both biases folded in
                #pragma unroll
                for (int nb = 0; nb < NB; nb++)
                    sRZ[nb * (2 * HH) + j] = sh[nb] + si[nb] + bihv + bhhv;
            } else {
                // n rows: x_n and g_n must stay separate (n = tanh(x_n + r*g_n))
                const int i = j - 2 * HH;
                #pragma unroll
                for (int nb = 0; nb < NB; nb++) {
                    sXN[nb * HH + i] = si[nb] + bihv;
                    sGN[nb * HH + i] = sh[nb] + bhhv;
                }
            }
        } else {
            // ---------- aux phase: prefetch x(t+1) into the other buffer ----------
            const int u = tid - GG;
            if (t + 1 < TT) {
                #pragma unroll
                for (int r = 0; r < 2; r++) {
                    int idx = u + r * 128;
                    if (idx < NB * DD) {
                        int nb = idx / DD, d = idx - nb * DD;
                        sX[nxt * (NB * DP) + nb * DP + d] =
                            history[(size_t)(b0 + nb) * (TT * DD) + (t + 1) * DD + d];
                    }
                }
            }
        }

        __syncthreads();  // gates written; x(t+1) staged

        if (tid >= GG) {
            // ---------- update phase: nonlinearities + h update ----------
            const int i = tid - GG;           // hidden index
            const float* hc = sH + cur * (NB * HH);
            float* hn = sH + nxt * (NB * HH);
            #pragma unroll
            for (int nb = 0; nb < NB; nb++) {
                float r = sigf(sRZ[nb * (2 * HH) + i]);
                float z = sigf(sRZ[nb * (2 * HH) + HH + i]);
                float n = tanhf(sXN[nb * HH + i] + r * sGN[nb * HH + i]);
                float hv = n + z * (hc[nb * HH + i] - n);
                hn[nb * HH + i] = hv;
                if (t == TT - 1)
                    out[(size_t)(b0 + nb) * HH + i] = hv;
            }
        }

        __syncthreads();  // h(t+1) visible to gate threads
    }
}

extern "C" void kernel_launch(void* const* d_in, const int* in_sizes, int n_in,
                              void* d_out, int out_size) {
    const float* history = (const float*)d_in[0];
    const float* W_ih    = (const float*)d_in[1];
    const float* W_hh    = (const float*)d_in[2];
    const float* b_ih    = (const float*)d_in[3];
    const float* b_hh    = (const float*)d_in[4];
    const float* h0      = (const float*)d_in[5];
    float* out = (float*)d_out;

    cudaFuncSetAttribute(gru_fused_kernel,
                         cudaFuncAttributeMaxDynamicSharedMemorySize, SMEM_BYTES);
    gru_fused_kernel<<<NCTA, NTHR, SMEM_BYTES>>>(history, W_ih, W_hh,
                                                 b_ih, b_hh, h0, out);
}

// round 3
// speedup vs baseline: 1.6402x; 1.6402x over previous
#include <cuda_runtime.h>

// GRU_83906481094863 — fused persistent GRU on sm_100a, v2 (crossbar-optimized).
// B=512, T=1024, D=46, H=128. 128 CTAs x 192 threads, NB=4 batches/CTA.
//   threads [0,128): gate threads, 4 warps = 1/SMSP. Thread u owns gate rows
//     {u, u+128, u+256} = (r,z,n) of hidden unit u -> full gate nonlinearity
//     and h-update computed IN REGISTER, h' stored straight to shared.
//     W_hh from shared (k-chunk-major, coalesced LDS.128), W_ih rows in regs,
//     all MACs via packed fma.rn.f32x2.
//   threads [128,192): aux, prefetch x(t+1).
// ONE __syncthreads per timestep.

#define BB 512
#define TT 1024
#define DD 46
#define DP 48        // D padded to 48 (pads zero)
#define HH 128
#define GG 384       // 3*H
#define NB 4
#define NCTA (BB/NB) // 128
#define NTHR 192
#define NGATE 128

// Shared (floats): sW[49152] W_hh k-chunk-major; sH[2][NB][HH]=1024; sX[2][NB][DP]=384
#define SMEM_FLOATS (49152 + 1024 + 384)
#define SMEM_BYTES  (SMEM_FLOATS * 4)

__device__ __forceinline__ void fma2(unsigned long long &d,
                                     unsigned long long a,
                                     unsigned long long b) {
    asm("fma.rn.f32x2 %0, %1, %2, %0;" : "+l"(d) : "l"(a), "l"(b));
}
__device__ __forceinline__ float sum2(unsigned long long v) {
    float lo, hi;
    asm("mov.b64 {%0, %1}, %2;" : "=f"(lo), "=f"(hi) : "l"(v));
    return lo + hi;
}
__device__ __forceinline__ unsigned long long pack2(float lo, float hi) {
    unsigned long long v;
    asm("mov.b64 %0, {%1, %2};" : "=l"(v) : "f"(lo), "f"(hi));
    return v;
}
__device__ __forceinline__ float sigf(float x) {
    return 0.5f + 0.5f * tanhf(0.5f * x);
}

__global__ void __launch_bounds__(NTHR, 1) gru_fused_v2(
    const float* __restrict__ history,  // [B][T][D]
    const float* __restrict__ W_ih,     // [3H][D]
    const float* __restrict__ W_hh,     // [3H][H]
    const float* __restrict__ b_ih,     // [3H]
    const float* __restrict__ b_hh,     // [3H]
    const float* __restrict__ h0,       // [H]
    float* __restrict__ out)            // [B][H]
{
    extern __shared__ float smem[];
    float* sW = smem;            // float4 view: chunk kc, row j -> (kc*GG + j)
    float* sH = smem + 49152;    // [2][NB][HH]
    float* sX = sH + 1024;       // [2][NB][DP]

    const int tid = threadIdx.x;
    const int b0  = blockIdx.x * NB;

    // ---- stage W_hh k-chunk-major ----
    for (int idx = tid; idx < GG * HH; idx += NTHR) {
        int j = idx >> 7;      // gate row
        int k = idx & 127;     // k index
        sW[((k >> 2) * GG + j) * 4 + (k & 3)] = W_hh[idx];
    }
    // ---- h(0) = h0 broadcast over batches ----
    for (int idx = tid; idx < NB * HH; idx += NTHR)
        sH[idx] = h0[idx & 127];
    // ---- zero x pads (both buffers) ----
    if (tid < 16) {
        int buf = tid >> 3, nb = (tid >> 1) & 3, d = DD + (tid & 1);
        sX[buf * (NB * DP) + nb * DP + d] = 0.f;
    }
    // ---- x(0) into buffer 0 ----
    for (int idx = tid; idx < NB * DD; idx += NTHR) {
        int nb = idx / DD, d = idx - nb * DD;
        sX[nb * DP + d] = history[(size_t)(b0 + nb) * (TT * DD) + d];
    }

    // ---- gate-thread private state ----
    const int u = tid;  // hidden unit (valid when tid < NGATE)
    unsigned long long wih[3][24];
    float bi[3], bh[3];
    if (tid < NGATE) {
        #pragma unroll
        for (int g = 0; g < 3; g++) {
            const int j = u + g * HH;
            bi[g] = b_ih[j];
            bh[g] = b_hh[j];
            #pragma unroll
            for (int p = 0; p < 23; p++)
                wih[g][p] = pack2(W_ih[j * DD + 2 * p], W_ih[j * DD + 2 * p + 1]);
            wih[g][23] = 0ull;   // k = 46,47 pads
        }
    }

    __syncthreads();

    for (int t = 0; t < TT; t++) {
        const int cur = t & 1, nxt = cur ^ 1;

        if (tid < NGATE) {
            const float* hb = sH + cur * (NB * HH);
            const float* xb = sX + cur * (NB * DP);
            const ulonglong2* wv = (const ulonglong2*)sW;

            unsigned long long ah[3][NB], ai[3][NB];
            #pragma unroll
            for (int g = 0; g < 3; g++)
                #pragma unroll
                for (int nb = 0; nb < NB; nb++) { ah[g][nb] = 0ull; ai[g][nb] = 0ull; }

            // ---- W_hh dot: 32 k-chunks of 4 ----
            #pragma unroll 8
            for (int kc = 0; kc < 32; kc++) {
                ulonglong2 w0 = wv[kc * GG + u];
                ulonglong2 w1 = wv[kc * GG + u + HH];
                ulonglong2 w2 = wv[kc * GG + u + 2 * HH];
                ulonglong2 hA = *(const ulonglong2*)(hb + 0 * HH + kc * 4);
                ulonglong2 hB = *(const ulonglong2*)(hb + 1 * HH + kc * 4);
                ulonglong2 hC = *(const ulonglong2*)(hb + 2 * HH + kc * 4);
                ulonglong2 hD = *(const ulonglong2*)(hb + 3 * HH + kc * 4);
                fma2(ah[0][0], w0.x, hA.x); fma2(ah[0][0], w0.y, hA.y);
                fma2(ah[0][1], w0.x, hB.x); fma2(ah[0][1], w0.y, hB.y);
                fma2(ah[0][2], w0.x, hC.x); fma2(ah[0][2], w0.y, hC.y);
                fma2(ah[0][3], w0.x, hD.x); fma2(ah[0][3], w0.y, hD.y);
                fma2(ah[1][0], w1.x, hA.x); fma2(ah[1][0], w1.y, hA.y);
                fma2(ah[1][1], w1.x, hB.x); fma2(ah[1][1], w1.y, hB.y);
                fma2(ah[1][2], w1.x, hC.x); fma2(ah[1][2], w1.y, hC.y);
                fma2(ah[1][3], w1.x, hD.x); fma2(ah[1][3], w1.y, hD.y);
                fma2(ah[2][0], w2.x, hA.x); fma2(ah[2][0], w2.y, hA.y);
                fma2(ah[2][1], w2.x, hB.x); fma2(ah[2][1], w2.y, hB.y);
                fma2(ah[2][2], w2.x, hC.x); fma2(ah[2][2], w2.y, hC.y);
                fma2(ah[2][3], w2.x, hD.x); fma2(ah[2][3], w2.y, hD.y);
            }
            // ---- W_ih dot: 12 x-chunks of 4 (pads zero) ----
            #pragma unroll
            for (int q = 0; q < 12; q++) {
                ulonglong2 xA = *(const ulonglong2*)(xb + 0 * DP + 4 * q);
                ulonglong2 xB = *(const ulonglong2*)(xb + 1 * DP + 4 * q);
                ulonglong2 xC = *(const ulonglong2*)(xb + 2 * DP + 4 * q);
                ulonglong2 xD = *(const ulonglong2*)(xb + 3 * DP + 4 * q);
                #pragma unroll
                for (int g = 0; g < 3; g++) {
                    unsigned long long wa = wih[g][2 * q], wb = wih[g][2 * q + 1];
                    fma2(ai[g][0], wa, xA.x); fma2(ai[g][0], wb, xA.y);
                    fma2(ai[g][1], wa, xB.x); fma2(ai[g][1], wb, xB.y);
                    fma2(ai[g][2], wa, xC.x); fma2(ai[g][2], wb, xC.y);
                    fma2(ai[g][3], wa, xD.x); fma2(ai[g][3], wb, xD.y);
                }
            }

            // ---- nonlinearity + h update, fully in-register ----
            float* hn = sH + nxt * (NB * HH);
            #pragma unroll
            for (int nb = 0; nb < NB; nb++) {
                float g_r = sum2(ah[0][nb]) + bh[0];
                float g_z = sum2(ah[1][nb]) + bh[1];
                float g_n = sum2(ah[2][nb]) + bh[2];
                float x_r = sum2(ai[0][nb]) + bi[0];
                float x_z = sum2(ai[1][nb]) + bi[1];
                float x_n = sum2(ai[2][nb]) + bi[2];
                float r = sigf(x_r + g_r);
                float z = sigf(x_z + g_z);
                float n = tanhf(x_n + r * g_n);
                float hold = hb[nb * HH + u];
                float hv = n + z * (hold - n);
                hn[nb * HH + u] = hv;
                if (t == TT - 1)
                    out[(size_t)(b0 + nb) * HH + u] = hv;
            }
        } else {
            // ---- aux: prefetch x(t+1) ----
            if (t + 1 < TT) {
                const int a = tid - NGATE;   // 0..63
                #pragma unroll
                for (int r = 0; r < 3; r++) {
                    int idx = a + r * 64;
                    if (idx < NB * DD) {
                        int nb = idx / DD, d = idx - nb * DD;
                        sX[nxt * (NB * DP) + nb * DP + d] =
                            history[(size_t)(b0 + nb) * (TT * DD) + (t + 1) * DD + d];
                    }
                }
            }
        }

        __syncthreads();   // h(t+1) + x(t+1) visible to everyone
    }
}

extern "C" void kernel_launch(void* const* d_in, const int* in_sizes, int n_in,
                              void* d_out, int out_size) {
    const float* history = (const float*)d_in[0];
    const float* W_ih    = (const float*)d_in[1];
    const float* W_hh    = (const float*)d_in[2];
    const float* b_ih    = (const float*)d_in[3];
    const float* b_hh    = (const float*)d_in[4];
    const float* h0      = (const float*)d_in[5];
    float* out = (float*)d_out;

    cudaFuncSetAttribute(gru_fused_v2,
                         cudaFuncAttributeMaxDynamicSharedMemorySize, SMEM_BYTES);
    gru_fused_v2<<<NCTA, NTHR, SMEM_BYTES>>>(history, W_ih, W_hh,
                                             b_ih, b_hh, h0, out);
}